// round 1
// baseline (speedup 1.0000x reference)
#include <cuda_runtime.h>
#include <cuda_bf16.h>

// Problem constants
#define B_   16
#define SQ_  128
#define SV_  128
#define DQ_  512
#define DV_  512
#define U_   256

// Scratch (static device allocations are allowed; cudaMalloc is not)
__device__ float g_s1[B_ * SQ_ * U_];      // [2048][256]
__device__ float g_s2[B_ * SV_ * U_];      // [2048][256]
__device__ float g_score[B_ * SQ_ * SV_];  // [16][128][128]

// ---------------------------------------------------------------------------
// Kernel A: fused dual GEMM.  z=0: s1 = query@W1+b1 ; z=1: s2 = values@W2+b2
// M=2048, K=512, N=256.  64x64 tile, k-tile 16, 256 threads, 4x4 per thread.
// ---------------------------------------------------------------------------
__global__ __launch_bounds__(256) void gemm_kernel(
    const float* __restrict__ query,
    const float* __restrict__ values,
    const float* __restrict__ W1, const float* __restrict__ b1,
    const float* __restrict__ W2, const float* __restrict__ b2)
{
    __shared__ float sA[16][68];   // padded, transposed A tile [k][m]
    __shared__ float sB[16][64];   // W tile [k][n]

    const int tid = threadIdx.x;
    const int z   = blockIdx.z;
    const float* __restrict__ A    = z ? values : query;  // [2048][512]
    const float* __restrict__ W    = z ? W2 : W1;         // [512][256]
    const float* __restrict__ bias = z ? b2 : b1;         // [256]
    float* __restrict__ C          = z ? g_s2 : g_s1;     // [2048][256]

    const int m0 = blockIdx.y * 64;
    const int n0 = blockIdx.x * 64;

    const int arow = tid >> 2;            // 0..63
    const int ak4  = (tid & 3) << 2;      // 0,4,8,12
    const int brow = tid >> 4;            // 0..15
    const int bn4  = (tid & 15) << 2;     // 0..60

    const int tmg = tid >> 4;             // 0..15
    const int tng = tid & 15;             // 0..15

    float acc[4][4];
#pragma unroll
    for (int i = 0; i < 4; i++)
#pragma unroll
        for (int j = 0; j < 4; j++) acc[i][j] = 0.f;

    for (int kt = 0; kt < DQ_; kt += 16) {
        // load A tile (64 x 16), transpose into sA[k][m]
        float4 av = *(const float4*)&A[(m0 + arow) * DQ_ + kt + ak4];
        sA[ak4 + 0][arow] = av.x;
        sA[ak4 + 1][arow] = av.y;
        sA[ak4 + 2][arow] = av.z;
        sA[ak4 + 3][arow] = av.w;
        // load W tile (16 x 64)
        float4 bv = *(const float4*)&W[(kt + brow) * U_ + n0 + bn4];
        *(float4*)&sB[brow][bn4] = bv;
        __syncthreads();

#pragma unroll
        for (int kk = 0; kk < 16; kk++) {
            float4 a = *(const float4*)&sA[kk][tmg << 2];
            float4 b = *(const float4*)&sB[kk][tng << 2];
            float ar[4] = {a.x, a.y, a.z, a.w};
            float br[4] = {b.x, b.y, b.z, b.w};
#pragma unroll
            for (int i = 0; i < 4; i++)
#pragma unroll
                for (int j = 0; j < 4; j++)
                    acc[i][j] = fmaf(ar[i], br[j], acc[i][j]);
        }
        __syncthreads();
    }

    float4 bb = *(const float4*)&bias[n0 + (tng << 2)];
#pragma unroll
    for (int i = 0; i < 4; i++) {
        float4 out;
        out.x = acc[i][0] + bb.x;
        out.y = acc[i][1] + bb.y;
        out.z = acc[i][2] + bb.z;
        out.w = acc[i][3] + bb.w;
        *(float4*)&C[(m0 + (tmg << 2) + i) * U_ + n0 + (tng << 2)] = out;
    }
}

// ---------------------------------------------------------------------------
// Kernel B: score[b,q,v] = Vb + sum_u tanh(s1[b,q,u] + s2[b,v,u]) * Vw[u]
// Block: 32x32 (q,v) tile, 256 threads, u processed in chunks of 64 in smem.
// Each thread: v = tid%32, q = (tid/32)*4 .. +3  (4 accumulators).
// ---------------------------------------------------------------------------
__device__ __forceinline__ float tanh_acc(float x) {
    float ax = fabsf(x);
    float e  = __expf(-2.f * ax);                    // in (0,1], no overflow
    float t  = __fdividef(1.f - e, 1.f + e);
    return copysignf(t, x);
}

__global__ __launch_bounds__(256) void score_kernel(
    const float* __restrict__ Vw, const float* __restrict__ Vb)
{
    __shared__ float sS1[32][65];
    __shared__ float sS2[32][65];
    __shared__ float sVw[64];

    const int tid = threadIdx.x;
    const int b   = blockIdx.z;
    const int q0  = blockIdx.y * 32;
    const int v0  = blockIdx.x * 32;

    const int tx = tid & 31;        // v within tile
    const int ty = tid >> 5;        // 0..7 -> q group

    const int lr  = tid >> 4;       // 0..15 load row
    const int lc4 = (tid & 15) << 2;

    float acc[4] = {0.f, 0.f, 0.f, 0.f};

    for (int u0 = 0; u0 < U_; u0 += 64) {
#pragma unroll
        for (int rr = lr; rr < 32; rr += 16) {
            float4 v1 = *(const float4*)&g_s1[((b * SQ_) + q0 + rr) * U_ + u0 + lc4];
            sS1[rr][lc4 + 0] = v1.x; sS1[rr][lc4 + 1] = v1.y;
            sS1[rr][lc4 + 2] = v1.z; sS1[rr][lc4 + 3] = v1.w;
            float4 v2 = *(const float4*)&g_s2[((b * SV_) + v0 + rr) * U_ + u0 + lc4];
            sS2[rr][lc4 + 0] = v2.x; sS2[rr][lc4 + 1] = v2.y;
            sS2[rr][lc4 + 2] = v2.z; sS2[rr][lc4 + 3] = v2.w;
        }
        if (tid < 64) sVw[tid] = Vw[u0 + tid];
        __syncthreads();

#pragma unroll 8
        for (int uu = 0; uu < 64; uu++) {
            float s2v = sS2[tx][uu];
            float vw  = sVw[uu];
#pragma unroll
            for (int i = 0; i < 4; i++) {
                float t = tanh_acc(sS1[ty * 4 + i][uu] + s2v);
                acc[i] = fmaf(t, vw, acc[i]);
            }
        }
        __syncthreads();
    }

    float vb = Vb[0];
#pragma unroll
    for (int i = 0; i < 4; i++) {
        int q = q0 + ty * 4 + i;
        g_score[((b * SQ_) + q) * SV_ + v0 + tx] = acc[i] + vb;
    }
}

// ---------------------------------------------------------------------------
// Kernel C: softmax over v + context = attn @ values, plus write both outputs.
// Block: (b, 16-row q tile), 256 threads.
//   Phase 1: 8 warps, 2 softmax rows each; weights -> smem + global out.
//   Phase 2: GEMM 16x512 = w[16x128] @ values[b][128x512], float4 on d.
// ---------------------------------------------------------------------------
__global__ __launch_bounds__(256) void out_kernel(
    const float* __restrict__ values,
    float* __restrict__ out_ctx,   // [B,SQ,DV]
    float* __restrict__ out_w)     // [B,SQ,SV]
{
    __shared__ float sW[16][128];

    const int tid = threadIdx.x;
    const int b   = blockIdx.y;
    const int q0  = blockIdx.x * 16;

    const int warp = tid >> 5;
    const int lane = tid & 31;

    // Phase 1: softmax rows q0 + 2*warp, q0 + 2*warp + 1
#pragma unroll
    for (int rr = 0; rr < 2; rr++) {
        const int r = 2 * warp + rr;
        const int q = q0 + r;
        const float* srow = &g_score[((b * SQ_) + q) * SV_];
        float sc[4];
#pragma unroll
        for (int j = 0; j < 4; j++) sc[j] = srow[lane + 32 * j];
        float m = fmaxf(fmaxf(sc[0], sc[1]), fmaxf(sc[2], sc[3]));
#pragma unroll
        for (int o = 16; o > 0; o >>= 1)
            m = fmaxf(m, __shfl_xor_sync(0xFFFFFFFFu, m, o));
        float e[4], s = 0.f;
#pragma unroll
        for (int j = 0; j < 4; j++) { e[j] = __expf(sc[j] - m); s += e[j]; }
#pragma unroll
        for (int o = 16; o > 0; o >>= 1)
            s += __shfl_xor_sync(0xFFFFFFFFu, s, o);
        float inv = __fdividef(1.f, s);
#pragma unroll
        for (int j = 0; j < 4; j++) {
            float w = e[j] * inv;
            sW[r][lane + 32 * j] = w;
            out_w[((b * SQ_) + q) * SV_ + lane + 32 * j] = w;
        }
    }
    __syncthreads();

    // Phase 2: context tile [16][512]
    const int tq = tid >> 7;        // 0..1
    const int td = tid & 127;       // 0..127 -> d = td*4

    float4 acc[8];
#pragma unroll
    for (int i = 0; i < 8; i++) acc[i] = make_float4(0.f, 0.f, 0.f, 0.f);

    const float* vb = &values[b * SV_ * DV_];
#pragma unroll 4
    for (int v = 0; v < SV_; v++) {
        float4 vv = *(const float4*)&vb[v * DV_ + (td << 2)];
#pragma unroll
        for (int i = 0; i < 8; i++) {
            float w = sW[tq * 8 + i][v];
            acc[i].x = fmaf(w, vv.x, acc[i].x);
            acc[i].y = fmaf(w, vv.y, acc[i].y);
            acc[i].z = fmaf(w, vv.z, acc[i].z);
            acc[i].w = fmaf(w, vv.w, acc[i].w);
        }
    }

#pragma unroll
    for (int i = 0; i < 8; i++) {
        int q = q0 + tq * 8 + i;
        *(float4*)&out_ctx[((b * SQ_) + q) * DV_ + (td << 2)] = acc[i];
    }
}

// ---------------------------------------------------------------------------
extern "C" void kernel_launch(void* const* d_in, const int* in_sizes, int n_in,
                              void* d_out, int out_size)
{
    const float* query  = (const float*)d_in[0];
    const float* values = (const float*)d_in[1];
    const float* W1     = (const float*)d_in[2];
    const float* b1     = (const float*)d_in[3];
    const float* W2     = (const float*)d_in[4];
    const float* b2     = (const float*)d_in[5];
    const float* Vw     = (const float*)d_in[6];
    const float* Vb     = (const float*)d_in[7];

    float* out_ctx = (float*)d_out;                      // [16,128,512]
    float* out_w   = out_ctx + B_ * SQ_ * DV_;           // [16,128,128,1]

    // s1 / s2 GEMMs (fused in one launch, z selects which)
    gemm_kernel<<<dim3(U_ / 64, (B_ * SQ_) / 64, 2), 256>>>(
        query, values, W1, b1, W2, b2);

    // score = reduce_u tanh(s1+s2)*Vw + Vb
    score_kernel<<<dim3(SV_ / 32, SQ_ / 32, B_), 256>>>(Vw, Vb);

    // softmax + context + outputs
    out_kernel<<<dim3(SQ_ / 16, B_), 256>>>(values, out_ctx, out_w);
}

// round 4
// speedup vs baseline: 1.2919x; 1.2919x over previous
#include <cuda_runtime.h>
#include <cuda_bf16.h>
#include <cstdint>

// Problem constants
#define B_   16
#define SQ_  128
#define SV_  128
#define DQ_  512
#define DV_  512
#define U_   256

// ---------------------------------------------------------------------------
// Scratch (__device__ globals — no allocation APIs allowed)
// ---------------------------------------------------------------------------
__device__ float g_s1[B_ * SQ_ * U_];      // [2048][256]
__device__ float g_s2[B_ * SV_ * U_];      // [2048][256]
__device__ float g_score[B_ * SQ_ * SV_];  // [16][128][128]

// Fragment-native packed operands for the mma.sync GEMMs.
// A (query/values): [z][rowblock(128)][kstep(32)][lane(32)] -> uint4 {a0,a1,a2,a3}
//   hi and lo in separate arrays (each LDG.128 per fragment).
// B (W^T):          [z][nblock(32)][kstep(32)][lane(32)]   -> uint4 {b0h,b1h,b0l,b1l}
__device__ uint4 g_Ahp[2][128 * 32 * 32];
__device__ uint4 g_Alp[2][128 * 32 * 32];
__device__ uint4 g_Wp [2][ 32 * 32 * 32];

// ---------------------------------------------------------------------------
// mma.sync m16n8k16 bf16 (row.col), fp32 accumulate — base sm_80+ feature,
// compiles at target sm_103 (no 'a'-suffix features used anywhere).
// ---------------------------------------------------------------------------
__device__ __forceinline__ void mma_bf16(float* d, const uint32_t* a,
                                         uint32_t b0, uint32_t b1) {
    asm volatile(
        "mma.sync.aligned.m16n8k16.row.col.f32.bf16.bf16.f32 "
        "{%0,%1,%2,%3}, {%4,%5,%6,%7}, {%8,%9}, {%0,%1,%2,%3};"
        : "+f"(d[0]), "+f"(d[1]), "+f"(d[2]), "+f"(d[3])
        : "r"(a[0]), "r"(a[1]), "r"(a[2]), "r"(a[3]), "r"(b0), "r"(b1));
}

__device__ __forceinline__ uint32_t split_pack(float x0, float x1, uint32_t& lo_pack) {
    __nv_bfloat16 h0 = __float2bfloat16(x0);
    __nv_bfloat16 h1 = __float2bfloat16(x1);
    float r0 = x0 - __bfloat162float(h0);
    float r1 = x1 - __bfloat162float(h1);
    __nv_bfloat16 l0 = __float2bfloat16(r0);
    __nv_bfloat16 l1 = __float2bfloat16(r1);
    lo_pack = ((uint32_t)__bfloat16_as_ushort(l1) << 16) | __bfloat16_as_ushort(l0);
    return ((uint32_t)__bfloat16_as_ushort(h1) << 16) | __bfloat16_as_ushort(h0);
}

// ---------------------------------------------------------------------------
// Kernel 0: fp32 -> bf16 (hi, lo) split into fragment-native packed layouts.
// grid (2048, 4): y=0 query, y=1 values, y=2 W1, y=3 W2 (W transposed to [n][k]).
// ---------------------------------------------------------------------------
__global__ __launch_bounds__(256) void convert_kernel(
    const float* __restrict__ q, const float* __restrict__ v,
    const float* __restrict__ W1, const float* __restrict__ W2)
{
    const int z = blockIdx.y;
    const int i = blockIdx.x * 256 + threadIdx.x;

    if (z < 2) {
        // A operands: one thread handles 2 consecutive k of one row.
        const float* src = z ? v : q;                  // [2048][512]
        uint32_t* dh = (uint32_t*)g_Ahp[z];
        uint32_t* dl = (uint32_t*)g_Alp[z];
        const int row = i >> 8;           // 0..2047
        const int k2  = (i & 255) << 1;   // even k
        float x0 = src[row * 512 + k2];
        float x1 = src[row * 512 + k2 + 1];
        uint32_t lp, hp = split_pack(x0, x1, lp);

        const int rb = row >> 4, r = row & 15;
        const int ks = k2 >> 4, kk = k2 & 15;
        const int tg = (kk >> 1) & 3;
        const int s  = ((kk >> 3) << 1) | (r >> 3);    // fragment slot a0..a3
        const int lane = ((r & 7) << 2) | tg;
        const int idx4 = (rb * 32 + ks) * 32 + lane;
        dh[idx4 * 4 + s] = hp;
        dl[idx4 * 4 + s] = lp;
    } else {
        if (i >= U_ * DQ_ / 2) return;                 // 131072 work items
        const float* src = (z == 3) ? W2 : W1;         // [512][256]
        uint32_t* dw = (uint32_t*)g_Wp[z - 2];
        const int n  = i & 255;                        // coalesced reads over n
        const int k2 = (i >> 8) << 1;
        float x0 = src[k2 * 256 + n];
        float x1 = src[(k2 + 1) * 256 + n];
        uint32_t lp, hp = split_pack(x0, x1, lp);

        const int nb = n >> 3, g = n & 7;
        const int ks = k2 >> 4, kk = k2 & 15;
        const int tg = (kk >> 1) & 3;
        const int bslot = kk >> 3;                     // 0 -> b0, 1 -> b1
        const int lane = (g << 2) | tg;
        const int idx4 = (nb * 32 + ks) * 32 + lane;
        dw[idx4 * 4 + bslot]     = hp;
        dw[idx4 * 4 + 2 + bslot] = lp;
    }
}

// ---------------------------------------------------------------------------
// Kernel A: tensor-core GEMM via mma.sync (bf16 hi/lo split, fp32 accum).
// C[2048,256] = A[2048,512] @ W[512,256] + bias, z=0 -> s1, z=1 -> s2.
// CTA tile 128m x 64n, 8 warps (4m x 2n), warp tile 32x32.
// All operands fetched directly from L2 in fragment-native layout (no smem).
// Grid (4, 16, 2) = 128 CTAs.
// ---------------------------------------------------------------------------
__global__ __launch_bounds__(256) void gemm_mma_kernel(
    const float* __restrict__ b1, const float* __restrict__ b2)
{
    const int tid  = threadIdx.x;
    const int wid  = tid >> 5;
    const int lane = tid & 31;
    const int g    = lane >> 2;
    const int tg   = lane & 3;

    const int z  = blockIdx.z;
    const int m0 = blockIdx.y * 128;
    const int n0 = blockIdx.x * 64;

    const uint4* __restrict__ Ah = g_Ahp[z];
    const uint4* __restrict__ Al = g_Alp[z];
    const uint4* __restrict__ Bp = g_Wp[z];
    float* __restrict__ C            = z ? g_s2 : g_s1;
    const float* __restrict__ bias   = z ? b2 : b1;

    const int warp_m = wid & 3;          // 4 warps over m (32 rows each)
    const int warp_n = wid >> 2;         // 2 warps over n (32 cols each)
    const int rb0 = (m0 >> 4) + warp_m * 2;   // 2 row-blocks (mt)
    const int nb0 = (n0 >> 3) + warp_n * 4;   // 4 n-blocks (nt)

    float acc[2][4][4];
#pragma unroll
    for (int mt = 0; mt < 2; mt++)
#pragma unroll
        for (int nt = 0; nt < 4; nt++)
#pragma unroll
            for (int c = 0; c < 4; c++) acc[mt][nt][c] = 0.f;

#pragma unroll 2
    for (int ks = 0; ks < 32; ks++) {
        uint4 AH[2], AL[2], Bf[4];
#pragma unroll
        for (int mt = 0; mt < 2; mt++) {
            AH[mt] = Ah[((rb0 + mt) * 32 + ks) * 32 + lane];
            AL[mt] = Al[((rb0 + mt) * 32 + ks) * 32 + lane];
        }
#pragma unroll
        for (int nt = 0; nt < 4; nt++)
            Bf[nt] = Bp[((nb0 + nt) * 32 + ks) * 32 + lane];

#pragma unroll
        for (int mt = 0; mt < 2; mt++)
#pragma unroll
            for (int nt = 0; nt < 4; nt++) {
                mma_bf16(acc[mt][nt], (const uint32_t*)&AH[mt], Bf[nt].x, Bf[nt].y); // hi*hi
                mma_bf16(acc[mt][nt], (const uint32_t*)&AH[mt], Bf[nt].z, Bf[nt].w); // hi*lo
                mma_bf16(acc[mt][nt], (const uint32_t*)&AL[mt], Bf[nt].x, Bf[nt].y); // lo*hi
            }
    }

    // Epilogue: add bias, write fp32 C.
#pragma unroll
    for (int mt = 0; mt < 2; mt++) {
        const int row = m0 + warp_m * 32 + mt * 16 + g;
#pragma unroll
        for (int nt = 0; nt < 4; nt++) {
            const int col = n0 + warp_n * 32 + nt * 8 + tg * 2;
            const float2 bb = *(const float2*)&bias[col];
            float2 o0, o1;
            o0.x = acc[mt][nt][0] + bb.x;
            o0.y = acc[mt][nt][1] + bb.y;
            o1.x = acc[mt][nt][2] + bb.x;
            o1.y = acc[mt][nt][3] + bb.y;
            *(float2*)&C[(size_t)row * U_ + col]       = o0;
            *(float2*)&C[(size_t)(row + 8) * U_ + col] = o1;
        }
    }
}

// ---------------------------------------------------------------------------
// Kernel B: score[b,q,v] = Vb + sum_u tanh(s1[b,q,u] + s2[b,v,u]) * Vw[u]
// tanh.approx.f32 (single MUFU.TANH per element) — MUFU-throughput bound.
// ---------------------------------------------------------------------------
__device__ __forceinline__ float tanh_fast(float x) {
    float y;
    asm("tanh.approx.f32 %0, %1;" : "=f"(y) : "f"(x));
    return y;
}

__global__ __launch_bounds__(256) void score_kernel(
    const float* __restrict__ Vw, const float* __restrict__ Vb)
{
    __shared__ float sS1[32][65];
    __shared__ float sS2[32][65];
    __shared__ float sVw[64];

    const int tid = threadIdx.x;
    const int b   = blockIdx.z;
    const int q0  = blockIdx.y * 32;
    const int v0  = blockIdx.x * 32;

    const int tx = tid & 31;        // v within tile
    const int ty = tid >> 5;        // q group

    const int lr  = tid >> 4;
    const int lc4 = (tid & 15) << 2;

    float acc[4] = {0.f, 0.f, 0.f, 0.f};

    for (int u0 = 0; u0 < U_; u0 += 64) {
#pragma unroll
        for (int rr = lr; rr < 32; rr += 16) {
            float4 v1 = *(const float4*)&g_s1[((b * SQ_) + q0 + rr) * U_ + u0 + lc4];
            sS1[rr][lc4 + 0] = v1.x; sS1[rr][lc4 + 1] = v1.y;
            sS1[rr][lc4 + 2] = v1.z; sS1[rr][lc4 + 3] = v1.w;
            float4 v2 = *(const float4*)&g_s2[((b * SV_) + v0 + rr) * U_ + u0 + lc4];
            sS2[rr][lc4 + 0] = v2.x; sS2[rr][lc4 + 1] = v2.y;
            sS2[rr][lc4 + 2] = v2.z; sS2[rr][lc4 + 3] = v2.w;
        }
        if (tid < 64) sVw[tid] = Vw[u0 + tid];
        __syncthreads();

#pragma unroll 8
        for (int uu = 0; uu < 64; uu++) {
            float s2v = sS2[tx][uu];
            float vw  = sVw[uu];
#pragma unroll
            for (int i = 0; i < 4; i++) {
                float t = tanh_fast(sS1[ty * 4 + i][uu] + s2v);
                acc[i] = fmaf(t, vw, acc[i]);
            }
        }
        __syncthreads();
    }

    const float vb = Vb[0];
#pragma unroll
    for (int i = 0; i < 4; i++) {
        int q = q0 + ty * 4 + i;
        g_score[((b * SQ_) + q) * SV_ + v0 + tx] = acc[i] + vb;
    }
}

// ---------------------------------------------------------------------------
// Kernel C: softmax over v + context = attn @ values + write both outputs.
// ---------------------------------------------------------------------------
__global__ __launch_bounds__(256) void out_kernel(
    const float* __restrict__ values,
    float* __restrict__ out_ctx,   // [B,SQ,DV]
    float* __restrict__ out_w)     // [B,SQ,SV]
{
    __shared__ float sW[16][128];

    const int tid = threadIdx.x;
    const int b   = blockIdx.y;
    const int q0  = blockIdx.x * 16;

    const int warp = tid >> 5;
    const int lane = tid & 31;

#pragma unroll
    for (int rr = 0; rr < 2; rr++) {
        const int r = 2 * warp + rr;
        const int q = q0 + r;
        const float* srow = &g_score[((b * SQ_) + q) * SV_];
        float sc[4];
#pragma unroll
        for (int j = 0; j < 4; j++) sc[j] = srow[lane + 32 * j];
        float m = fmaxf(fmaxf(sc[0], sc[1]), fmaxf(sc[2], sc[3]));
#pragma unroll
        for (int o = 16; o > 0; o >>= 1)
            m = fmaxf(m, __shfl_xor_sync(0xFFFFFFFFu, m, o));
        float e[4], s = 0.f;
#pragma unroll
        for (int j = 0; j < 4; j++) { e[j] = __expf(sc[j] - m); s += e[j]; }
#pragma unroll
        for (int o = 16; o > 0; o >>= 1)
            s += __shfl_xor_sync(0xFFFFFFFFu, s, o);
        float inv = __fdividef(1.f, s);
#pragma unroll
        for (int j = 0; j < 4; j++) {
            float w = e[j] * inv;
            sW[r][lane + 32 * j] = w;
            out_w[((b * SQ_) + q) * SV_ + lane + 32 * j] = w;
        }
    }
    __syncthreads();

    const int tq = tid >> 7;
    const int td = tid & 127;

    float4 acc[8];
#pragma unroll
    for (int i = 0; i < 8; i++) acc[i] = make_float4(0.f, 0.f, 0.f, 0.f);

    const float* vb = &values[b * SV_ * DV_];
#pragma unroll 4
    for (int v = 0; v < SV_; v++) {
        float4 vv = *(const float4*)&vb[v * DV_ + (td << 2)];
#pragma unroll
        for (int i = 0; i < 8; i++) {
            float w = sW[tq * 8 + i][v];
            acc[i].x = fmaf(w, vv.x, acc[i].x);
            acc[i].y = fmaf(w, vv.y, acc[i].y);
            acc[i].z = fmaf(w, vv.z, acc[i].z);
            acc[i].w = fmaf(w, vv.w, acc[i].w);
        }
    }

#pragma unroll
    for (int i = 0; i < 8; i++) {
        int q = q0 + tq * 8 + i;
        *(float4*)&out_ctx[((b * SQ_) + q) * DV_ + (td << 2)] = acc[i];
    }
}

// ---------------------------------------------------------------------------
extern "C" void kernel_launch(void* const* d_in, const int* in_sizes, int n_in,
                              void* d_out, int out_size)
{
    const float* query  = (const float*)d_in[0];
    const float* values = (const float*)d_in[1];
    const float* W1     = (const float*)d_in[2];
    const float* b1     = (const float*)d_in[3];
    const float* W2     = (const float*)d_in[4];
    const float* b2     = (const float*)d_in[5];
    const float* Vw     = (const float*)d_in[6];
    const float* Vb     = (const float*)d_in[7];

    float* out_ctx = (float*)d_out;                      // [16,128,512]
    float* out_w   = out_ctx + B_ * SQ_ * DV_;           // [16,128,128,1]

    // fp32 -> bf16 hi/lo split into fragment-native packed layouts
    convert_kernel<<<dim3(2048, 4), 256>>>(query, values, W1, W2);

    // tensor-core GEMMs: s1 = q@W1+b1, s2 = v@W2+b2
    gemm_mma_kernel<<<dim3(4, 16, 2), 256>>>(b1, b2);

    // score = reduce_u tanh(s1+s2)*Vw + Vb
    score_kernel<<<dim3(SV_ / 32, SQ_ / 32, B_), 256>>>(Vw, Vb);

    // softmax + context + outputs
    out_kernel<<<dim3(SQ_ / 16, B_), 256>>>(values, out_ctx, out_w);
}

// round 5
// speedup vs baseline: 1.3279x; 1.0278x over previous
#include <cuda_runtime.h>
#include <cuda_bf16.h>
#include <cstdint>

// Problem constants
#define B_   16
#define SQ_  128
#define SV_  128
#define DQ_  512
#define DV_  512
#define U_   256

// ---------------------------------------------------------------------------
// Scratch (__device__ globals — no allocation APIs allowed)
// ---------------------------------------------------------------------------
__device__ float g_s1[B_ * SQ_ * U_];      // [2048][256]
__device__ float g_s2[B_ * SV_ * U_];      // [2048][256]
__device__ float g_score[B_ * SQ_ * SV_];  // [16][128][128]

// Fragment-native packed operands for the mma.sync GEMMs.
__device__ uint4 g_Ahp[2][128 * 32 * 32];
__device__ uint4 g_Alp[2][128 * 32 * 32];
__device__ uint4 g_Wp [2][ 32 * 32 * 32];

// ---------------------------------------------------------------------------
// mma.sync m16n8k16 bf16 (row.col), fp32 accumulate — base sm_80+ feature.
// ---------------------------------------------------------------------------
__device__ __forceinline__ void mma_bf16(float* d, const uint32_t* a,
                                         uint32_t b0, uint32_t b1) {
    asm volatile(
        "mma.sync.aligned.m16n8k16.row.col.f32.bf16.bf16.f32 "
        "{%0,%1,%2,%3}, {%4,%5,%6,%7}, {%8,%9}, {%0,%1,%2,%3};"
        : "+f"(d[0]), "+f"(d[1]), "+f"(d[2]), "+f"(d[3])
        : "r"(a[0]), "r"(a[1]), "r"(a[2]), "r"(a[3]), "r"(b0), "r"(b1));
}

__device__ __forceinline__ uint32_t split_pack(float x0, float x1, uint32_t& lo_pack) {
    __nv_bfloat16 h0 = __float2bfloat16(x0);
    __nv_bfloat16 h1 = __float2bfloat16(x1);
    float r0 = x0 - __bfloat162float(h0);
    float r1 = x1 - __bfloat162float(h1);
    __nv_bfloat16 l0 = __float2bfloat16(r0);
    __nv_bfloat16 l1 = __float2bfloat16(r1);
    lo_pack = ((uint32_t)__bfloat16_as_ushort(l1) << 16) | __bfloat16_as_ushort(l0);
    return ((uint32_t)__bfloat16_as_ushort(h1) << 16) | __bfloat16_as_ushort(h0);
}

// ---------------------------------------------------------------------------
// Kernel 0: fp32 -> bf16 (hi, lo) split into fragment-native packed layouts.
// grid (2048, 4): y=0 query, y=1 values, y=2 W1, y=3 W2 (W transposed to [n][k]).
// ---------------------------------------------------------------------------
__global__ __launch_bounds__(256) void convert_kernel(
    const float* __restrict__ q, const float* __restrict__ v,
    const float* __restrict__ W1, const float* __restrict__ W2)
{
    const int z = blockIdx.y;
    const int i = blockIdx.x * 256 + threadIdx.x;

    if (z < 2) {
        const float* src = z ? v : q;                  // [2048][512]
        uint32_t* dh = (uint32_t*)g_Ahp[z];
        uint32_t* dl = (uint32_t*)g_Alp[z];
        const int row = i >> 8;           // 0..2047
        const int k2  = (i & 255) << 1;   // even k
        float x0 = src[row * 512 + k2];
        float x1 = src[row * 512 + k2 + 1];
        uint32_t lp, hp = split_pack(x0, x1, lp);

        const int rb = row >> 4, r = row & 15;
        const int ks = k2 >> 4, kk = k2 & 15;
        const int tg = (kk >> 1) & 3;
        const int s  = ((kk >> 3) << 1) | (r >> 3);    // fragment slot a0..a3
        const int lane = ((r & 7) << 2) | tg;
        const int idx4 = (rb * 32 + ks) * 32 + lane;
        dh[idx4 * 4 + s] = hp;
        dl[idx4 * 4 + s] = lp;
    } else {
        if (i >= U_ * DQ_ / 2) return;
        const float* src = (z == 3) ? W2 : W1;         // [512][256]
        uint32_t* dw = (uint32_t*)g_Wp[z - 2];
        const int n  = i & 255;
        const int k2 = (i >> 8) << 1;
        float x0 = src[k2 * 256 + n];
        float x1 = src[(k2 + 1) * 256 + n];
        uint32_t lp, hp = split_pack(x0, x1, lp);

        const int nb = n >> 3, g = n & 7;
        const int ks = k2 >> 4, kk = k2 & 15;
        const int tg = (kk >> 1) & 3;
        const int bslot = kk >> 3;
        const int lane = (g << 2) | tg;
        const int idx4 = (nb * 32 + ks) * 32 + lane;
        dw[idx4 * 4 + bslot]     = hp;
        dw[idx4 * 4 + 2 + bslot] = lp;
    }
}

// ---------------------------------------------------------------------------
// Kernel A: tensor-core GEMM via mma.sync (bf16 hi/lo split, fp32 accum).
// C[2048,256] = A[2048,512] @ W[512,256] + bias, z=0 -> s1, z=1 -> s2.
// CTA tile 128m x 64n, 8 warps (4m x 2n), operands straight from L2.
// ---------------------------------------------------------------------------
__global__ __launch_bounds__(256) void gemm_mma_kernel(
    const float* __restrict__ b1, const float* __restrict__ b2)
{
    const int tid  = threadIdx.x;
    const int wid  = tid >> 5;
    const int lane = tid & 31;
    const int g    = lane >> 2;
    const int tg   = lane & 3;

    const int z  = blockIdx.z;
    const int m0 = blockIdx.y * 128;
    const int n0 = blockIdx.x * 64;

    const uint4* __restrict__ Ah = g_Ahp[z];
    const uint4* __restrict__ Al = g_Alp[z];
    const uint4* __restrict__ Bp = g_Wp[z];
    float* __restrict__ C            = z ? g_s2 : g_s1;
    const float* __restrict__ bias   = z ? b2 : b1;

    const int warp_m = wid & 3;
    const int warp_n = wid >> 2;
    const int rb0 = (m0 >> 4) + warp_m * 2;
    const int nb0 = (n0 >> 3) + warp_n * 4;

    float acc[2][4][4];
#pragma unroll
    for (int mt = 0; mt < 2; mt++)
#pragma unroll
        for (int nt = 0; nt < 4; nt++)
#pragma unroll
            for (int c = 0; c < 4; c++) acc[mt][nt][c] = 0.f;

#pragma unroll 2
    for (int ks = 0; ks < 32; ks++) {
        uint4 AH[2], AL[2], Bf[4];
#pragma unroll
        for (int mt = 0; mt < 2; mt++) {
            AH[mt] = Ah[((rb0 + mt) * 32 + ks) * 32 + lane];
            AL[mt] = Al[((rb0 + mt) * 32 + ks) * 32 + lane];
        }
#pragma unroll
        for (int nt = 0; nt < 4; nt++)
            Bf[nt] = Bp[((nb0 + nt) * 32 + ks) * 32 + lane];

#pragma unroll
        for (int mt = 0; mt < 2; mt++)
#pragma unroll
            for (int nt = 0; nt < 4; nt++) {
                mma_bf16(acc[mt][nt], (const uint32_t*)&AH[mt], Bf[nt].x, Bf[nt].y);
                mma_bf16(acc[mt][nt], (const uint32_t*)&AH[mt], Bf[nt].z, Bf[nt].w);
                mma_bf16(acc[mt][nt], (const uint32_t*)&AL[mt], Bf[nt].x, Bf[nt].y);
            }
    }

#pragma unroll
    for (int mt = 0; mt < 2; mt++) {
        const int row = m0 + warp_m * 32 + mt * 16 + g;
#pragma unroll
        for (int nt = 0; nt < 4; nt++) {
            const int col = n0 + warp_n * 32 + nt * 8 + tg * 2;
            const float2 bb = *(const float2*)&bias[col];
            float2 o0, o1;
            o0.x = acc[mt][nt][0] + bb.x;
            o0.y = acc[mt][nt][1] + bb.y;
            o1.x = acc[mt][nt][2] + bb.x;
            o1.y = acc[mt][nt][3] + bb.y;
            *(float2*)&C[(size_t)row * U_ + col]       = o0;
            *(float2*)&C[(size_t)(row + 8) * U_ + col] = o1;
        }
    }
}

// ---------------------------------------------------------------------------
// Kernel B: score[b,q,v] = Vb + sum_u tanh(s1[b,q,u] + s2[b,v,u]) * Vw[u]
// ---------------------------------------------------------------------------
__device__ __forceinline__ float tanh_fast(float x) {
    float y;
    asm("tanh.approx.f32 %0, %1;" : "=f"(y) : "f"(x));
    return y;
}

__global__ __launch_bounds__(256) void score_kernel(
    const float* __restrict__ Vw, const float* __restrict__ Vb)
{
    __shared__ float sS1[32][65];
    __shared__ float sS2[32][65];
    __shared__ float sVw[64];

    const int tid = threadIdx.x;
    const int b   = blockIdx.z;
    const int q0  = blockIdx.y * 32;
    const int v0  = blockIdx.x * 32;

    const int tx = tid & 31;
    const int ty = tid >> 5;

    const int lr  = tid >> 4;
    const int lc4 = (tid & 15) << 2;

    float acc[4] = {0.f, 0.f, 0.f, 0.f};

    for (int u0 = 0; u0 < U_; u0 += 64) {
#pragma unroll
        for (int rr = lr; rr < 32; rr += 16) {
            float4 v1 = *(const float4*)&g_s1[((b * SQ_) + q0 + rr) * U_ + u0 + lc4];
            sS1[rr][lc4 + 0] = v1.x; sS1[rr][lc4 + 1] = v1.y;
            sS1[rr][lc4 + 2] = v1.z; sS1[rr][lc4 + 3] = v1.w;
            float4 v2 = *(const float4*)&g_s2[((b * SV_) + v0 + rr) * U_ + u0 + lc4];
            sS2[rr][lc4 + 0] = v2.x; sS2[rr][lc4 + 1] = v2.y;
            sS2[rr][lc4 + 2] = v2.z; sS2[rr][lc4 + 3] = v2.w;
        }
        if (tid < 64) sVw[tid] = Vw[u0 + tid];
        __syncthreads();

#pragma unroll 8
        for (int uu = 0; uu < 64; uu++) {
            float s2v = sS2[tx][uu];
            float vw  = sVw[uu];
#pragma unroll
            for (int i = 0; i < 4; i++) {
                float t = tanh_fast(sS1[ty * 4 + i][uu] + s2v);
                acc[i] = fmaf(t, vw, acc[i]);
            }
        }
        __syncthreads();
    }

    const float vb = Vb[0];
#pragma unroll
    for (int i = 0; i < 4; i++) {
        int q = q0 + ty * 4 + i;
        g_score[((b * SQ_) + q) * SV_ + v0 + tx] = acc[i] + vb;
    }
}

// ---------------------------------------------------------------------------
// Kernel C1: row softmax.  One warp per (b,q) row; 8 rows per block.
// Reads g_score, writes normalized weights to out_w.
// ---------------------------------------------------------------------------
__global__ __launch_bounds__(256) void softmax_kernel(float* __restrict__ out_w)
{
    const int tid  = threadIdx.x;
    const int warp = tid >> 5;
    const int lane = tid & 31;
    const int row  = blockIdx.x * 8 + warp;      // 0..2047 = b*128+q

    const float* srow = &g_score[row * SV_];
    float sc[4];
#pragma unroll
    for (int j = 0; j < 4; j++) sc[j] = srow[lane + 32 * j];
    float m = fmaxf(fmaxf(sc[0], sc[1]), fmaxf(sc[2], sc[3]));
#pragma unroll
    for (int o = 16; o > 0; o >>= 1)
        m = fmaxf(m, __shfl_xor_sync(0xFFFFFFFFu, m, o));
    float e[4], s = 0.f;
#pragma unroll
    for (int j = 0; j < 4; j++) { e[j] = __expf(sc[j] - m); s += e[j]; }
#pragma unroll
    for (int o = 16; o > 0; o >>= 1)
        s += __shfl_xor_sync(0xFFFFFFFFu, s, o);
    float inv = __fdividef(1.f, s);
#pragma unroll
    for (int j = 0; j < 4; j++)
        out_w[row * SV_ + lane + 32 * j] = e[j] * inv;
}

// ---------------------------------------------------------------------------
// Kernel C2: context = attn @ values.
// Tile: 32 q x 128 d per block; grid (4 dtile, 4 qtile, 16 b) = 256 blocks.
// Weights tile (32x128) staged in smem; each warp owns one q-group of 4 rows,
// so the per-iteration sW reads are uniform (broadcast, conflict-free).
// values float4 loads are coalesced and L1-shared across the 8 q-warps.
// ---------------------------------------------------------------------------
__global__ __launch_bounds__(256) void ctx_kernel(
    const float* __restrict__ values,
    const float* __restrict__ out_w,
    float* __restrict__ out_ctx)
{
    __shared__ float sW[32][128];

    const int tid = threadIdx.x;
    const int b   = blockIdx.z;
    const int q0  = blockIdx.y * 32;
    const int d0  = blockIdx.x * 128;

    // Load weight tile [32 q][128 v] (float4, fully coalesced)
#pragma unroll
    for (int k = 0; k < 4; k++) {
        const int idx = tid + k * 256;       // 0..1023
        const int r   = idx >> 5;            // q row 0..31
        const int c4  = idx & 31;            // float4 col
        float4 w = *(const float4*)&out_w[((b * SQ_) + q0 + r) * SV_ + (c4 << 2)];
        *(float4*)&sW[r][c4 << 2] = w;
    }
    __syncthreads();

    const int dg = tid & 31;                 // d float4 group
    const int qg = tid >> 5;                 // warp = q group (4 rows)

    float4 acc[4];
#pragma unroll
    for (int i = 0; i < 4; i++) acc[i] = make_float4(0.f, 0.f, 0.f, 0.f);

    const float* vb = &values[(size_t)b * SV_ * DV_ + d0 + (dg << 2)];
#pragma unroll 4
    for (int v = 0; v < SV_; v++) {
        float4 vv = *(const float4*)&vb[(size_t)v * DV_];
#pragma unroll
        for (int i = 0; i < 4; i++) {
            float w = sW[qg * 4 + i][v];     // uniform within warp -> broadcast
            acc[i].x = fmaf(w, vv.x, acc[i].x);
            acc[i].y = fmaf(w, vv.y, acc[i].y);
            acc[i].z = fmaf(w, vv.z, acc[i].z);
            acc[i].w = fmaf(w, vv.w, acc[i].w);
        }
    }

#pragma unroll
    for (int i = 0; i < 4; i++) {
        const int q = q0 + qg * 4 + i;
        *(float4*)&out_ctx[((size_t)(b * SQ_) + q) * DV_ + d0 + (dg << 2)] = acc[i];
    }
}

// ---------------------------------------------------------------------------
extern "C" void kernel_launch(void* const* d_in, const int* in_sizes, int n_in,
                              void* d_out, int out_size)
{
    const float* query  = (const float*)d_in[0];
    const float* values = (const float*)d_in[1];
    const float* W1     = (const float*)d_in[2];
    const float* b1     = (const float*)d_in[3];
    const float* W2     = (const float*)d_in[4];
    const float* b2     = (const float*)d_in[5];
    const float* Vw     = (const float*)d_in[6];
    const float* Vb     = (const float*)d_in[7];

    float* out_ctx = (float*)d_out;                      // [16,128,512]
    float* out_w   = out_ctx + B_ * SQ_ * DV_;           // [16,128,128,1]

    // fp32 -> bf16 hi/lo split into fragment-native packed layouts
    convert_kernel<<<dim3(2048, 4), 256>>>(query, values, W1, W2);

    // tensor-core GEMMs: s1 = q@W1+b1, s2 = v@W2+b2
    gemm_mma_kernel<<<dim3(4, 16, 2), 256>>>(b1, b2);

    // score = reduce_u tanh(s1+s2)*Vw + Vb
    score_kernel<<<dim3(SV_ / 32, SQ_ / 32, B_), 256>>>(Vw, Vb);

    // softmax -> out_w
    softmax_kernel<<<256, 256>>>(out_w);

    // context = attn @ values -> out_ctx
    ctx_kernel<<<dim3(4, 4, 16), 256>>>(values, out_w, out_ctx);
}

// round 6
// speedup vs baseline: 1.4221x; 1.0710x over previous
#include <cuda_runtime.h>
#include <cuda_bf16.h>
#include <cstdint>

// Problem constants
#define B_   16
#define SQ_  128
#define SV_  128
#define DQ_  512
#define DV_  512
#define U_   256

// ---------------------------------------------------------------------------
// Scratch (__device__ globals — no allocation APIs allowed)
// ---------------------------------------------------------------------------
__device__ float g_s1[B_ * SQ_ * U_];      // [2048][256]
__device__ float g_s2[B_ * SV_ * U_];      // [2048][256]
__device__ float g_score[B_ * SQ_ * SV_];  // [16][128][128]

// Fragment-native packed operands for the mma.sync GEMMs.
__device__ uint4 g_Ahp[2][128 * 32 * 32];
__device__ uint4 g_Alp[2][128 * 32 * 32];
__device__ uint4 g_Wp [2][ 32 * 32 * 32];

// ---------------------------------------------------------------------------
// Helpers
// ---------------------------------------------------------------------------
__device__ __forceinline__ uint32_t smem_u32(const void* p) {
    uint32_t a;
    asm("{ .reg .u64 t; cvta.to.shared.u64 t, %1; cvt.u32.u64 %0, t; }"
        : "=r"(a) : "l"(p));
    return a;
}
__device__ __forceinline__ void cp_async16(uint32_t s, const void* g) {
    asm volatile("cp.async.cg.shared.global [%0], [%1], 16;" :: "r"(s), "l"(g));
}
#define CP_COMMIT()  asm volatile("cp.async.commit_group;" ::: "memory")
#define CP_WAIT0()   asm volatile("cp.async.wait_group 0;" ::: "memory")

// mma.sync m16n8k16 bf16 (row.col), fp32 accumulate — base sm_80+ feature.
__device__ __forceinline__ void mma_bf16(float* d, const uint32_t* a,
                                         uint32_t b0, uint32_t b1) {
    asm volatile(
        "mma.sync.aligned.m16n8k16.row.col.f32.bf16.bf16.f32 "
        "{%0,%1,%2,%3}, {%4,%5,%6,%7}, {%8,%9}, {%0,%1,%2,%3};"
        : "+f"(d[0]), "+f"(d[1]), "+f"(d[2]), "+f"(d[3])
        : "r"(a[0]), "r"(a[1]), "r"(a[2]), "r"(a[3]), "r"(b0), "r"(b1));
}

__device__ __forceinline__ uint32_t split_pack(float x0, float x1, uint32_t& lo_pack) {
    __nv_bfloat16 h0 = __float2bfloat16(x0);
    __nv_bfloat16 h1 = __float2bfloat16(x1);
    float r0 = x0 - __bfloat162float(h0);
    float r1 = x1 - __bfloat162float(h1);
    __nv_bfloat16 l0 = __float2bfloat16(r0);
    __nv_bfloat16 l1 = __float2bfloat16(r1);
    lo_pack = ((uint32_t)__bfloat16_as_ushort(l1) << 16) | __bfloat16_as_ushort(l0);
    return ((uint32_t)__bfloat16_as_ushort(h1) << 16) | __bfloat16_as_ushort(h0);
}

// ---------------------------------------------------------------------------
// Kernel 0: fp32 -> bf16 (hi, lo) split into fragment-native packed layouts.
// grid (2048, 4): y=0 query, y=1 values, y=2 W1, y=3 W2 (W transposed to [n][k]).
// ---------------------------------------------------------------------------
__global__ __launch_bounds__(256) void convert_kernel(
    const float* __restrict__ q, const float* __restrict__ v,
    const float* __restrict__ W1, const float* __restrict__ W2)
{
    const int z = blockIdx.y;
    const int i = blockIdx.x * 256 + threadIdx.x;

    if (z < 2) {
        const float* src = z ? v : q;                  // [2048][512]
        uint32_t* dh = (uint32_t*)g_Ahp[z];
        uint32_t* dl = (uint32_t*)g_Alp[z];
        const int row = i >> 8;           // 0..2047
        const int k2  = (i & 255) << 1;   // even k
        float x0 = src[row * 512 + k2];
        float x1 = src[row * 512 + k2 + 1];
        uint32_t lp, hp = split_pack(x0, x1, lp);

        const int rb = row >> 4, r = row & 15;
        const int ks = k2 >> 4, kk = k2 & 15;
        const int tg = (kk >> 1) & 3;
        const int s  = ((kk >> 3) << 1) | (r >> 3);    // fragment slot a0..a3
        const int lane = ((r & 7) << 2) | tg;
        const int idx4 = (rb * 32 + ks) * 32 + lane;
        dh[idx4 * 4 + s] = hp;
        dl[idx4 * 4 + s] = lp;
    } else {
        if (i >= U_ * DQ_ / 2) return;
        const float* src = (z == 3) ? W2 : W1;         // [512][256]
        uint32_t* dw = (uint32_t*)g_Wp[z - 2];
        const int n  = i & 255;
        const int k2 = (i >> 8) << 1;
        float x0 = src[k2 * 256 + n];
        float x1 = src[(k2 + 1) * 256 + n];
        uint32_t lp, hp = split_pack(x0, x1, lp);

        const int nb = n >> 3, g = n & 7;
        const int ks = k2 >> 4, kk = k2 & 15;
        const int tg = (kk >> 1) & 3;
        const int bslot = kk >> 3;
        const int lane = (g << 2) | tg;
        const int idx4 = (nb * 32 + ks) * 32 + lane;
        dw[idx4 * 4 + bslot]     = hp;
        dw[idx4 * 4 + 2 + bslot] = lp;
    }
}

// ---------------------------------------------------------------------------
// Kernel A: tensor-core GEMM via mma.sync (bf16 hi/lo split, fp32 accum).
// ---------------------------------------------------------------------------
__global__ __launch_bounds__(256) void gemm_mma_kernel(
    const float* __restrict__ b1, const float* __restrict__ b2)
{
    const int tid  = threadIdx.x;
    const int wid  = tid >> 5;
    const int lane = tid & 31;
    const int g    = lane >> 2;
    const int tg   = lane & 3;

    const int z  = blockIdx.z;
    const int m0 = blockIdx.y * 128;
    const int n0 = blockIdx.x * 64;

    const uint4* __restrict__ Ah = g_Ahp[z];
    const uint4* __restrict__ Al = g_Alp[z];
    const uint4* __restrict__ Bp = g_Wp[z];
    float* __restrict__ C            = z ? g_s2 : g_s1;
    const float* __restrict__ bias   = z ? b2 : b1;

    const int warp_m = wid & 3;
    const int warp_n = wid >> 2;
    const int rb0 = (m0 >> 4) + warp_m * 2;
    const int nb0 = (n0 >> 3) + warp_n * 4;

    float acc[2][4][4];
#pragma unroll
    for (int mt = 0; mt < 2; mt++)
#pragma unroll
        for (int nt = 0; nt < 4; nt++)
#pragma unroll
            for (int c = 0; c < 4; c++) acc[mt][nt][c] = 0.f;

#pragma unroll 2
    for (int ks = 0; ks < 32; ks++) {
        uint4 AH[2], AL[2], Bf[4];
#pragma unroll
        for (int mt = 0; mt < 2; mt++) {
            AH[mt] = Ah[((rb0 + mt) * 32 + ks) * 32 + lane];
            AL[mt] = Al[((rb0 + mt) * 32 + ks) * 32 + lane];
        }
#pragma unroll
        for (int nt = 0; nt < 4; nt++)
            Bf[nt] = Bp[((nb0 + nt) * 32 + ks) * 32 + lane];

#pragma unroll
        for (int mt = 0; mt < 2; mt++)
#pragma unroll
            for (int nt = 0; nt < 4; nt++) {
                mma_bf16(acc[mt][nt], (const uint32_t*)&AH[mt], Bf[nt].x, Bf[nt].y);
                mma_bf16(acc[mt][nt], (const uint32_t*)&AH[mt], Bf[nt].z, Bf[nt].w);
                mma_bf16(acc[mt][nt], (const uint32_t*)&AL[mt], Bf[nt].x, Bf[nt].y);
            }
    }

#pragma unroll
    for (int mt = 0; mt < 2; mt++) {
        const int row = m0 + warp_m * 32 + mt * 16 + g;
#pragma unroll
        for (int nt = 0; nt < 4; nt++) {
            const int col = n0 + warp_n * 32 + nt * 8 + tg * 2;
            const float2 bb = *(const float2*)&bias[col];
            float2 o0, o1;
            o0.x = acc[mt][nt][0] + bb.x;
            o0.y = acc[mt][nt][1] + bb.y;
            o1.x = acc[mt][nt][2] + bb.x;
            o1.y = acc[mt][nt][3] + bb.y;
            *(float2*)&C[(size_t)row * U_ + col]       = o0;
            *(float2*)&C[(size_t)(row + 8) * U_ + col] = o1;
        }
    }
}

// ---------------------------------------------------------------------------
// Kernel B: score[b,q,v] = Vb + sum_u tanh(s1[b,q,u] + s2[b,v,u]) * Vw[u]
// ---------------------------------------------------------------------------
__device__ __forceinline__ float tanh_fast(float x) {
    float y;
    asm("tanh.approx.f32 %0, %1;" : "=f"(y) : "f"(x));
    return y;
}

__global__ __launch_bounds__(256) void score_kernel(
    const float* __restrict__ Vw, const float* __restrict__ Vb)
{
    __shared__ float sS1[32][65];
    __shared__ float sS2[32][65];
    __shared__ float sVw[64];

    const int tid = threadIdx.x;
    const int b   = blockIdx.z;
    const int q0  = blockIdx.y * 32;
    const int v0  = blockIdx.x * 32;

    const int tx = tid & 31;
    const int ty = tid >> 5;

    const int lr  = tid >> 4;
    const int lc4 = (tid & 15) << 2;

    float acc[4] = {0.f, 0.f, 0.f, 0.f};

    for (int u0 = 0; u0 < U_; u0 += 64) {
#pragma unroll
        for (int rr = lr; rr < 32; rr += 16) {
            float4 v1 = *(const float4*)&g_s1[((b * SQ_) + q0 + rr) * U_ + u0 + lc4];
            sS1[rr][lc4 + 0] = v1.x; sS1[rr][lc4 + 1] = v1.y;
            sS1[rr][lc4 + 2] = v1.z; sS1[rr][lc4 + 3] = v1.w;
            float4 v2 = *(const float4*)&g_s2[((b * SV_) + v0 + rr) * U_ + u0 + lc4];
            sS2[rr][lc4 + 0] = v2.x; sS2[rr][lc4 + 1] = v2.y;
            sS2[rr][lc4 + 2] = v2.z; sS2[rr][lc4 + 3] = v2.w;
        }
        if (tid < 64) sVw[tid] = Vw[u0 + tid];
        __syncthreads();

#pragma unroll 8
        for (int uu = 0; uu < 64; uu++) {
            float s2v = sS2[tx][uu];
            float vw  = sVw[uu];
#pragma unroll
            for (int i = 0; i < 4; i++) {
                float t = tanh_fast(sS1[ty * 4 + i][uu] + s2v);
                acc[i] = fmaf(t, vw, acc[i]);
            }
        }
        __syncthreads();
    }

    const float vb = Vb[0];
#pragma unroll
    for (int i = 0; i < 4; i++) {
        int q = q0 + ty * 4 + i;
        g_score[((b * SQ_) + q) * SV_ + v0 + tx] = acc[i] + vb;
    }
}

// ---------------------------------------------------------------------------
// Kernel C1: row softmax.  One warp per (b,q) row; 8 rows per block.
// ---------------------------------------------------------------------------
__global__ __launch_bounds__(256) void softmax_kernel(float* __restrict__ out_w)
{
    const int tid  = threadIdx.x;
    const int warp = tid >> 5;
    const int lane = tid & 31;
    const int row  = blockIdx.x * 8 + warp;      // 0..2047 = b*128+q

    const float* srow = &g_score[row * SV_];
    float sc[4];
#pragma unroll
    for (int j = 0; j < 4; j++) sc[j] = srow[lane + 32 * j];
    float m = fmaxf(fmaxf(sc[0], sc[1]), fmaxf(sc[2], sc[3]));
#pragma unroll
    for (int o = 16; o > 0; o >>= 1)
        m = fmaxf(m, __shfl_xor_sync(0xFFFFFFFFu, m, o));
    float e[4], s = 0.f;
#pragma unroll
    for (int j = 0; j < 4; j++) { e[j] = __expf(sc[j] - m); s += e[j]; }
#pragma unroll
    for (int o = 16; o > 0; o >>= 1)
        s += __shfl_xor_sync(0xFFFFFFFFu, s, o);
    float inv = __fdividef(1.f, s);
#pragma unroll
    for (int j = 0; j < 4; j++)
        out_w[row * SV_ + lane + 32 * j] = e[j] * inv;
}

// ---------------------------------------------------------------------------
// Kernel C2: context = attn @ values, cp.async double-buffered smem staging.
// Tile: 32 q x 128 d per block; grid (4 dtile, 4 qtile, 16 b) = 256 blocks.
// values staged in 4 chunks of 32 v-rows (16 KB each); global latency hidden
// by the async pipeline; inner loop is pure LDS + FMA (FMA-bound).
// ---------------------------------------------------------------------------
__global__ __launch_bounds__(256) void ctx_kernel(
    const float* __restrict__ values,
    const float* __restrict__ out_w,
    float* __restrict__ out_ctx)
{
    __shared__ float sW[32][128];
    __shared__ float sV[2][32 * 128];

    const int tid = threadIdx.x;
    const int b   = blockIdx.z;
    const int q0  = blockIdx.y * 32;
    const int d0  = blockIdx.x * 128;

    const float* __restrict__ vsrc = values + (size_t)b * SV_ * DV_ + d0;
    const uint32_t svb = smem_u32(&sV[0][0]);

    // Issue chunk 0 (v rows 0..31) into buffer 0 before anything else.
#pragma unroll
    for (int k = 0; k < 4; k++) {
        const int idx = tid + k * 256;       // 0..1023 16B-chunks
        const int r   = idx >> 5;            // v row 0..31
        const int c4  = idx & 31;            // 16B col group
        cp_async16(svb + (uint32_t)(r * 128 + c4 * 4) * 4,
                   vsrc + (size_t)r * DV_ + c4 * 4);
    }
    CP_COMMIT();

    // Load weight tile [32 q][128 v] (float4, coalesced) — overlaps chunk 0.
#pragma unroll
    for (int k = 0; k < 4; k++) {
        const int idx = tid + k * 256;
        const int r   = idx >> 5;
        const int c4  = idx & 31;
        float4 w = *(const float4*)&out_w[((b * SQ_) + q0 + r) * SV_ + (c4 << 2)];
        *(float4*)&sW[r][c4 << 2] = w;
    }

    const int dg = tid & 31;                 // d float4 group
    const int qg = tid >> 5;                 // warp = q group (4 rows)

    float4 acc[4];
#pragma unroll
    for (int i = 0; i < 4; i++) acc[i] = make_float4(0.f, 0.f, 0.f, 0.f);

#pragma unroll
    for (int c = 0; c < 4; c++) {
        CP_WAIT0();
        __syncthreads();                     // chunk c ready; prior compute done

        if (c < 3) {                         // prefetch chunk c+1 into other buf
            const uint32_t nb = svb + (uint32_t)(((c + 1) & 1) * 32 * 128) * 4;
            const float* gsrc = vsrc + (size_t)(c + 1) * 32 * DV_;
#pragma unroll
            for (int k = 0; k < 4; k++) {
                const int idx = tid + k * 256;
                const int r   = idx >> 5;
                const int c4  = idx & 31;
                cp_async16(nb + (uint32_t)(r * 128 + c4 * 4) * 4,
                           gsrc + (size_t)r * DV_ + c4 * 4);
            }
            CP_COMMIT();
        }

        const float* sv = &sV[c & 1][0];
#pragma unroll
        for (int v = 0; v < 32; v++) {
            float4 vv = *(const float4*)&sv[v * 128 + (dg << 2)];
            const int gv = c * 32 + v;
#pragma unroll
            for (int i = 0; i < 4; i++) {
                float w = sW[qg * 4 + i][gv];    // uniform -> broadcast
                acc[i].x = fmaf(w, vv.x, acc[i].x);
                acc[i].y = fmaf(w, vv.y, acc[i].y);
                acc[i].z = fmaf(w, vv.z, acc[i].z);
                acc[i].w = fmaf(w, vv.w, acc[i].w);
            }
        }
        __syncthreads();                     // compute done before buf reuse
    }

#pragma unroll
    for (int i = 0; i < 4; i++) {
        const int q = q0 + qg * 4 + i;
        *(float4*)&out_ctx[((size_t)(b * SQ_) + q) * DV_ + d0 + (dg << 2)] = acc[i];
    }
}

// ---------------------------------------------------------------------------
extern "C" void kernel_launch(void* const* d_in, const int* in_sizes, int n_in,
                              void* d_out, int out_size)
{
    const float* query  = (const float*)d_in[0];
    const float* values = (const float*)d_in[1];
    const float* W1     = (const float*)d_in[2];
    const float* b1     = (const float*)d_in[3];
    const float* W2     = (const float*)d_in[4];
    const float* b2     = (const float*)d_in[5];
    const float* Vw     = (const float*)d_in[6];
    const float* Vb     = (const float*)d_in[7];

    float* out_ctx = (float*)d_out;                      // [16,128,512]
    float* out_w   = out_ctx + B_ * SQ_ * DV_;           // [16,128,128,1]

    // fp32 -> bf16 hi/lo split into fragment-native packed layouts
    convert_kernel<<<dim3(2048, 4), 256>>>(query, values, W1, W2);

    // tensor-core GEMMs: s1 = q@W1+b1, s2 = v@W2+b2
    gemm_mma_kernel<<<dim3(4, 16, 2), 256>>>(b1, b2);

    // score = reduce_u tanh(s1+s2)*Vw + Vb
    score_kernel<<<dim3(SV_ / 32, SQ_ / 32, B_), 256>>>(Vw, Vb);

    // softmax -> out_w
    softmax_kernel<<<256, 256>>>(out_w);

    // context = attn @ values -> out_ctx
    ctx_kernel<<<dim3(4, 4, 16), 256>>>(values, out_w, out_ctx);
}